// round 5
// baseline (speedup 1.0000x reference)
#include <cuda_runtime.h>
#include <cuda_bf16.h>
#include <math.h>

// Shapes
#define B_SZ 4096
#define P_SZ 256
#define F_SZ 20
#define H_SZ 18
#define W_SZ 18
#define HW   (H_SZ * W_SZ)          // 324
#define FHW  (F_SZ * HW)            // 6480
#define PI_C 3.14159f

// Scratch (no allocations allowed; use device globals)
__device__ float g_h[B_SZ * P_SZ];          // relu(pc @ W1 + b1)
__device__ float g_aff[B_SZ * F_SZ * 4];    // per (b,f): u, v, Bx, By

// ---------------------------------------------------------------------------
// Kernel 1: h = relu(pc @ W1 + b1).  M=4096, N=256, K=256.
// 64x64 tile, BK=16, 256 threads, 4x4 per thread.
// ---------------------------------------------------------------------------
__global__ void __launch_bounds__(256) gemm_relu_kernel(
    const float* __restrict__ A,      // (4096, 256)
    const float* __restrict__ W,      // (256, 256)
    const float* __restrict__ bias)   // (256)
{
    const int BM = 64, BN = 64, BK = 16;
    __shared__ float As[BK][BM + 4];  // [k][m]
    __shared__ float Bs[BK][BN];      // [k][n]

    int tid = threadIdx.x;
    int tx = tid & 15;
    int ty = tid >> 4;
    int row0 = blockIdx.x * BM;
    int col0 = blockIdx.y * BN;

    float acc[4][4];
#pragma unroll
    for (int i = 0; i < 4; i++)
#pragma unroll
        for (int j = 0; j < 4; j++) acc[i][j] = 0.f;

    for (int k0 = 0; k0 < P_SZ; k0 += BK) {
        {
            int m  = tid >> 2;
            int kq = (tid & 3) << 2;
            float4 v = *(const float4*)&A[(row0 + m) * P_SZ + k0 + kq];
            As[kq + 0][m] = v.x;
            As[kq + 1][m] = v.y;
            As[kq + 2][m] = v.z;
            As[kq + 3][m] = v.w;
        }
        {
            int k = tid >> 4;
            int n = (tid & 15) << 2;
            *(float4*)&Bs[k][n] = *(const float4*)&W[(k0 + k) * P_SZ + col0 + n];
        }
        __syncthreads();

#pragma unroll
        for (int k = 0; k < BK; k++) {
            float4 av = *(const float4*)&As[k][ty * 4];
            float4 bv = *(const float4*)&Bs[k][tx * 4];
            float a[4] = {av.x, av.y, av.z, av.w};
            float b[4] = {bv.x, bv.y, bv.z, bv.w};
#pragma unroll
            for (int i = 0; i < 4; i++)
#pragma unroll
                for (int j = 0; j < 4; j++)
                    acc[i][j] = fmaf(a[i], b[j], acc[i][j]);
        }
        __syncthreads();
    }

    int c = col0 + tx * 4;
    float4 bb = *(const float4*)&bias[c];
#pragma unroll
    for (int i = 0; i < 4; i++) {
        int r = row0 + ty * 4 + i;
        float4 v;
        v.x = fmaxf(acc[i][0] + bb.x, 0.f);
        v.y = fmaxf(acc[i][1] + bb.y, 0.f);
        v.z = fmaxf(acc[i][2] + bb.z, 0.f);
        v.w = fmaxf(acc[i][3] + bb.w, 0.f);
        *(float4*)&g_h[r * P_SZ + c] = v;
    }
}

// ---------------------------------------------------------------------------
// Kernel 2: raw = h @ [Ws|Wr|Wt] (4096x80 GEMM, K=256) + activations.
// BM=16 (grid 256 -> fills all 148 SMs), BK=32, 256 threads, 5 outs/thread.
// ---------------------------------------------------------------------------
__global__ void __launch_bounds__(256) params_kernel(
    const float* __restrict__ Ws, const float* __restrict__ bs,
    const float* __restrict__ Wr, const float* __restrict__ br,
    const float* __restrict__ Wt, const float* __restrict__ bt)
{
    __shared__ float hs[16][33];      // [m][k]
    __shared__ float ws[32][80];      // [k][j]
    __shared__ float raw[16][80];

    int tid = threadIdx.x;
    int b0 = blockIdx.x * 16;
    int ty = tid >> 4;                // 0..15 (row)
    int tx = tid & 15;                // 0..15 (col group of 5)

    float acc[5];
#pragma unroll
    for (int j = 0; j < 5; j++) acc[j] = 0.f;

    for (int k0 = 0; k0 < P_SZ; k0 += 32) {
        // h tile: 16x32 = 128 float4; threads 0..127
        if (tid < 128) {
            int m  = tid >> 3;            // 0..15
            int kq = (tid & 7) << 2;      // 0..28
            float4 v = *(const float4*)&g_h[(b0 + m) * P_SZ + k0 + kq];
            hs[m][kq + 0] = v.x;
            hs[m][kq + 1] = v.y;
            hs[m][kq + 2] = v.z;
            hs[m][kq + 3] = v.w;
        }
        // W tile: 32x80 (2560 scalars, 10/thread)
        for (int i = tid; i < 32 * 80; i += 256) {
            int k = i / 80;
            int j = i - k * 80;
            int kk = k0 + k;
            float w;
            if (j < 20)       w = Ws[kk * 20 + j];
            else if (j < 40)  w = Wr[kk * 20 + (j - 20)];
            else              w = Wt[kk * 40 + (j - 40)];
            ws[k][j] = w;
        }
        __syncthreads();

#pragma unroll
        for (int k = 0; k < 32; k++) {
            float a = hs[ty][k];
#pragma unroll
            for (int j = 0; j < 5; j++)
                acc[j] = fmaf(a, ws[k][tx * 5 + j], acc[j]);
        }
        __syncthreads();
    }

#pragma unroll
    for (int j = 0; j < 5; j++) raw[ty][tx * 5 + j] = acc[j];
    __syncthreads();

    // Activations: 16 rows x 20 channels = 320 outputs
    for (int o = tid; o < 16 * F_SZ; o += 256) {
        int bi = o / F_SZ, f = o - bi * F_SZ;
        float scale = 2.f / (1.f + expf(-(raw[bi][f] + bs[f])));
        float angle = tanhf(raw[bi][20 + f] + br[f]) * PI_C;
        float txn = tanhf(raw[bi][40 + 2 * f] + bt[2 * f]);
        float tyn = tanhf(raw[bi][41 + 2 * f] + bt[2 * f + 1]);
        float s, c;
        sincosf(angle, &s, &c);
        float4 r = make_float4(9.f * scale * c,
                               9.f * scale * s,
                               9.f * txn + 8.5f,
                               9.f * tyn + 8.5f);
        *(float4*)&g_aff[(b0 + bi) * 80 + f * 4] = r;
    }
}

// ---------------------------------------------------------------------------
// Kernel 3: trilinear sampling. One CTA per batch; 672 threads; thread = one
// (y,x) pixel x 10 channels (2 f-groups). Fully branchless taps: clamped
// indices + validity folded into weights -> 8 unconditional LDS per channel.
// ---------------------------------------------------------------------------
__global__ void __launch_bounds__(672) sample_kernel(
    const float* __restrict__ fmap,   // (B, 20, 18, 18)
    float* __restrict__ out)          // (B, 20, 18, 18)
{
    __shared__ float vol[FHW];
    __shared__ float4 affs[F_SZ];
    int b = blockIdx.x;
    int tid = threadIdx.x;

    const float4* fb4 = (const float4*)(fmap + b * FHW);
    float4* vol4 = (float4*)vol;
    for (int i = tid; i < FHW / 4; i += 672) vol4[i] = fb4[i];  // 1620 vec4
    if (tid < F_SZ) affs[tid] = *(const float4*)&g_aff[b * 80 + tid * 4];
    __syncthreads();

    if (tid >= 2 * HW) return;
    int g = (tid >= HW) ? 1 : 0;      // channel group: f in [g*10, g*10+10)
    int p = tid - g * HW;
    int y = p / W_SZ;
    int x = p - y * W_SZ;
    float gx = (2.f / 17.f) * x - 1.f;
    float gy = (2.f / 17.f) * y - 1.f;
    int fbase = g * 10;
    float* ob = out + b * FHW + p;

#pragma unroll
    for (int i = 0; i < 10; i++) {
        int f = fbase + i;
        // z interp (cheap runtime; only f=0 / f=19 hit a boundary)
        float iz = f * (20.f / 19.f) - 0.5f;
        float z0f = floorf(iz);
        float wz = iz - z0f;
        int z0 = (int)z0f;
        int zc0 = max(z0, 0);
        int zc1 = min(z0 + 1, F_SZ - 1);
        float w0 = (z0 >= 0) ? (1.f - wz) : 0.f;
        float w1 = (z0 + 1 <= F_SZ - 1) ? wz : 0.f;

        float4 A = affs[f];
        float ix = fmaf(A.x, gx, fmaf(-A.y, gy, A.z));
        float iy = fmaf(A.y, gx, fmaf(A.x, gy, A.w));

        float x0f = floorf(ix), y0f = floorf(iy);
        float wx = ix - x0f, wy = iy - y0f;
        int x0 = (int)x0f, y0 = (int)y0f;

        // clamped indices + validity masks (branchless)
        int xc0 = min(max(x0, 0), W_SZ - 1);
        int xc1 = min(max(x0 + 1, 0), W_SZ - 1);
        int yc0 = min(max(y0, 0), H_SZ - 1);
        int yc1 = min(max(y0 + 1, 0), H_SZ - 1);
        float wx0 = ((unsigned)x0       < (unsigned)W_SZ) ? (1.f - wx) : 0.f;
        float wx1 = ((unsigned)(x0 + 1) < (unsigned)W_SZ) ? wx         : 0.f;
        float wy0 = ((unsigned)y0       < (unsigned)H_SZ) ? (1.f - wy) : 0.f;
        float wy1 = ((unsigned)(y0 + 1) < (unsigned)H_SZ) ? wy         : 0.f;

        float a00 = wy0 * wx0, a01 = wy0 * wx1;
        float a10 = wy1 * wx0, a11 = wy1 * wx1;
        int o00 = yc0 * W_SZ + xc0, o01 = yc0 * W_SZ + xc1;
        int o10 = yc1 * W_SZ + xc0, o11 = yc1 * W_SZ + xc1;
        const float* pz0 = vol + zc0 * HW;
        const float* pz1 = vol + zc1 * HW;

        float bl0 = fmaf(a00, pz0[o00], fmaf(a01, pz0[o01],
                    fmaf(a10, pz0[o10], a11 * pz0[o11])));
        float bl1 = fmaf(a00, pz1[o00], fmaf(a01, pz1[o01],
                    fmaf(a10, pz1[o10], a11 * pz1[o11])));
        ob[f * HW] = fmaf(w0, bl0, w1 * bl1);
    }
}

// ---------------------------------------------------------------------------
extern "C" void kernel_launch(void* const* d_in, const int* in_sizes, int n_in,
                              void* d_out, int out_size)
{
    const float* fmap = (const float*)d_in[0];  // (4096, 20, 18, 18)
    const float* pc   = (const float*)d_in[1];  // (4096, 256)
    const float* W1   = (const float*)d_in[2];  // (256, 256)
    const float* b1   = (const float*)d_in[3];  // (256)
    const float* Ws   = (const float*)d_in[4];  // (256, 20)
    const float* bs   = (const float*)d_in[5];  // (20)
    const float* Wr   = (const float*)d_in[6];  // (256, 20)
    const float* br   = (const float*)d_in[7];  // (20)
    const float* Wt   = (const float*)d_in[8];  // (256, 40)
    const float* bt   = (const float*)d_in[9];  // (40)
    float* out = (float*)d_out;

    gemm_relu_kernel<<<dim3(B_SZ / 64, P_SZ / 64), 256>>>(pc, W1, b1);
    params_kernel<<<B_SZ / 16, 256>>>(Ws, bs, Wr, br, Wt, bt);
    sample_kernel<<<B_SZ, 672>>>(fmap, out);
}

// round 6
// speedup vs baseline: 1.3702x; 1.3702x over previous
#include <cuda_runtime.h>
#include <cuda_bf16.h>
#include <math.h>

// Shapes
#define B_SZ 4096
#define P_SZ 256
#define F_SZ 20
#define H_SZ 18
#define W_SZ 18
#define HW   (H_SZ * W_SZ)          // 324
#define FHW  (F_SZ * HW)            // 6480
#define PI_C 3.14159f

// Padded SMEM volume layout (odd row stride kills stride-36/18 bank conflicts)
#define ROWP   19
#define PLANEP (ROWP * H_SZ)        // 342
#define VOLP   (F_SZ * PLANEP)      // 6840 floats = 27.36 KB

// Scratch (no allocations allowed; use device globals)
__device__ float g_h[B_SZ * P_SZ];          // relu(pc @ W1 + b1)
__device__ float g_aff[B_SZ * F_SZ * 4];    // per (b,f): u, v, Bx, By

// ---------------------------------------------------------------------------
// Kernel 1: h = relu(pc @ W1 + b1).  M=4096, N=256, K=256.
// 64x64 tile, BK=16, 256 threads, 4x4 per thread.
// ---------------------------------------------------------------------------
__global__ void __launch_bounds__(256) gemm_relu_kernel(
    const float* __restrict__ A,      // (4096, 256)
    const float* __restrict__ W,      // (256, 256)
    const float* __restrict__ bias)   // (256)
{
    const int BM = 64, BN = 64, BK = 16;
    __shared__ float As[BK][BM + 4];
    __shared__ float Bs[BK][BN];

    int tid = threadIdx.x;
    int tx = tid & 15;
    int ty = tid >> 4;
    int row0 = blockIdx.x * BM;
    int col0 = blockIdx.y * BN;

    float acc[4][4];
#pragma unroll
    for (int i = 0; i < 4; i++)
#pragma unroll
        for (int j = 0; j < 4; j++) acc[i][j] = 0.f;

    for (int k0 = 0; k0 < P_SZ; k0 += BK) {
        {
            int m  = tid >> 2;
            int kq = (tid & 3) << 2;
            float4 v = *(const float4*)&A[(row0 + m) * P_SZ + k0 + kq];
            As[kq + 0][m] = v.x;
            As[kq + 1][m] = v.y;
            As[kq + 2][m] = v.z;
            As[kq + 3][m] = v.w;
        }
        {
            int k = tid >> 4;
            int n = (tid & 15) << 2;
            *(float4*)&Bs[k][n] = *(const float4*)&W[(k0 + k) * P_SZ + col0 + n];
        }
        __syncthreads();

#pragma unroll
        for (int k = 0; k < BK; k++) {
            float4 av = *(const float4*)&As[k][ty * 4];
            float4 bv = *(const float4*)&Bs[k][tx * 4];
            float a[4] = {av.x, av.y, av.z, av.w};
            float b[4] = {bv.x, bv.y, bv.z, bv.w};
#pragma unroll
            for (int i = 0; i < 4; i++)
#pragma unroll
                for (int j = 0; j < 4; j++)
                    acc[i][j] = fmaf(a[i], b[j], acc[i][j]);
        }
        __syncthreads();
    }

    int c = col0 + tx * 4;
    float4 bb = *(const float4*)&bias[c];
#pragma unroll
    for (int i = 0; i < 4; i++) {
        int r = row0 + ty * 4 + i;
        float4 v;
        v.x = fmaxf(acc[i][0] + bb.x, 0.f);
        v.y = fmaxf(acc[i][1] + bb.y, 0.f);
        v.z = fmaxf(acc[i][2] + bb.z, 0.f);
        v.w = fmaxf(acc[i][3] + bb.w, 0.f);
        *(float4*)&g_h[r * P_SZ + c] = v;
    }
}

// ---------------------------------------------------------------------------
// Kernel 2: raw = h @ [Ws|Wr|Wt] (4096x80 GEMM, K=256) + activations.
// BM=16 (grid 256 -> fills all 148 SMs), BK=32, 256 threads, 5 outs/thread.
// ---------------------------------------------------------------------------
__global__ void __launch_bounds__(256) params_kernel(
    const float* __restrict__ Ws, const float* __restrict__ bs,
    const float* __restrict__ Wr, const float* __restrict__ br,
    const float* __restrict__ Wt, const float* __restrict__ bt)
{
    __shared__ float hs[16][33];
    __shared__ float ws[32][80];
    __shared__ float raw[16][80];

    int tid = threadIdx.x;
    int b0 = blockIdx.x * 16;
    int ty = tid >> 4;
    int tx = tid & 15;

    float acc[5];
#pragma unroll
    for (int j = 0; j < 5; j++) acc[j] = 0.f;

    for (int k0 = 0; k0 < P_SZ; k0 += 32) {
        if (tid < 128) {
            int m  = tid >> 3;
            int kq = (tid & 7) << 2;
            float4 v = *(const float4*)&g_h[(b0 + m) * P_SZ + k0 + kq];
            hs[m][kq + 0] = v.x;
            hs[m][kq + 1] = v.y;
            hs[m][kq + 2] = v.z;
            hs[m][kq + 3] = v.w;
        }
        for (int i = tid; i < 32 * 80; i += 256) {
            int k = i / 80;
            int j = i - k * 80;
            int kk = k0 + k;
            float w;
            if (j < 20)       w = Ws[kk * 20 + j];
            else if (j < 40)  w = Wr[kk * 20 + (j - 20)];
            else              w = Wt[kk * 40 + (j - 40)];
            ws[k][j] = w;
        }
        __syncthreads();

#pragma unroll
        for (int k = 0; k < 32; k++) {
            float a = hs[ty][k];
#pragma unroll
            for (int j = 0; j < 5; j++)
                acc[j] = fmaf(a, ws[k][tx * 5 + j], acc[j]);
        }
        __syncthreads();
    }

#pragma unroll
    for (int j = 0; j < 5; j++) raw[ty][tx * 5 + j] = acc[j];
    __syncthreads();

    for (int o = tid; o < 16 * F_SZ; o += 256) {
        int bi = o / F_SZ, f = o - bi * F_SZ;
        float scale = 2.f / (1.f + expf(-(raw[bi][f] + bs[f])));
        float angle = tanhf(raw[bi][20 + f] + br[f]) * PI_C;
        float txn = tanhf(raw[bi][40 + 2 * f] + bt[2 * f]);
        float tyn = tanhf(raw[bi][41 + 2 * f] + bt[2 * f + 1]);
        float s, c;
        sincosf(angle, &s, &c);
        float4 r = make_float4(9.f * scale * c,
                               9.f * scale * s,
                               9.f * txn + 8.5f,
                               9.f * tyn + 8.5f);
        *(float4*)&g_aff[(b0 + bi) * 80 + f * 4] = r;
    }
}

// ---------------------------------------------------------------------------
// Kernel 3: trilinear sampling with conflict-reducing padded SMEM layout and
// compile-time-folded z interpolation. One CTA/batch, 672 threads; active
// thread = one (y,x) pixel x 10 channels.
// ---------------------------------------------------------------------------
template<int F>
__device__ __forceinline__ void sample_one(
    const float* __restrict__ vol, const float4* __restrict__ affs,
    float gx, float gy, float* __restrict__ ob)
{
    // z interpolation: z0 = f-1 for f<=9, z0 = f for f>=10; constants fold.
    constexpr int  z0  = (F <= 9) ? (F - 1) : F;
    constexpr bool h0  = (z0 >= 0);
    constexpr bool h1  = (z0 + 1 <= F_SZ - 1);
    const float iz = F * (20.f / 19.f) - 0.5f;
    const float wz = iz - (float)z0;           // compile-time constant
    const float w0 = h0 ? (1.f - wz) : 0.f;
    const float w1 = h1 ? wz : 0.f;

    float4 A = affs[F];                        // lane-uniform SMEM -> broadcast
    float ix = fmaf(A.x, gx, fmaf(-A.y, gy, A.z));
    float iy = fmaf(A.y, gx, fmaf(A.x, gy, A.w));

    float x0f = floorf(ix), y0f = floorf(iy);
    float wx = ix - x0f, wy = iy - y0f;
    int x0 = (int)x0f, y0 = (int)y0f;

    int xc0 = min(max(x0, 0), W_SZ - 1);
    int xc1 = min(max(x0 + 1, 0), W_SZ - 1);
    int yc0 = min(max(y0, 0), H_SZ - 1);
    int yc1 = min(max(y0 + 1, 0), H_SZ - 1);
    float wx0 = ((unsigned)x0       < (unsigned)W_SZ) ? (1.f - wx) : 0.f;
    float wx1 = ((unsigned)(x0 + 1) < (unsigned)W_SZ) ? wx         : 0.f;
    float wy0 = ((unsigned)y0       < (unsigned)H_SZ) ? (1.f - wy) : 0.f;
    float wy1 = ((unsigned)(y0 + 1) < (unsigned)H_SZ) ? wy         : 0.f;

    float a00 = wy0 * wx0, a01 = wy0 * wx1;
    float a10 = wy1 * wx0, a11 = wy1 * wx1;
    int r0 = yc0 * ROWP, r1 = yc1 * ROWP;
    int o00 = r0 + xc0, o01 = r0 + xc1;
    int o10 = r1 + xc0, o11 = r1 + xc1;

    float res;
    if (h0 && h1) {
        const float* pz0 = vol + z0 * PLANEP;
        const float* pz1 = vol + (z0 + 1) * PLANEP;
        float bl0 = fmaf(a00, pz0[o00], fmaf(a01, pz0[o01],
                    fmaf(a10, pz0[o10], a11 * pz0[o11])));
        float bl1 = fmaf(a00, pz1[o00], fmaf(a01, pz1[o01],
                    fmaf(a10, pz1[o10], a11 * pz1[o11])));
        res = fmaf(w0, bl0, w1 * bl1);
    } else {
        constexpr int zs = h0 ? z0 : 0;        // the single valid plane
        const float wzs = h0 ? w0 : w1;
        const float* pz = vol + zs * PLANEP;
        float bl = fmaf(a00, pz[o00], fmaf(a01, pz[o01],
                   fmaf(a10, pz[o10], a11 * pz[o11])));
        res = wzs * bl;
    }
    ob[F * HW] = res;
}

__global__ void __launch_bounds__(672) sample_kernel(
    const float* __restrict__ fmap,   // (B, 20, 18, 18)
    float* __restrict__ out)          // (B, 20, 18, 18)
{
    __shared__ float vol[VOLP];
    __shared__ float4 affs[F_SZ];
    int b = blockIdx.x;
    int tid = threadIdx.x;

    // Load dense volume (float4 coalesced) and scatter into padded layout.
    const float4* fb4 = (const float4*)(fmap + b * FHW);
    for (int i = tid; i < FHW / 4; i += 672) {
        float4 v = fb4[i];
        int d = i * 4;
        int z = d / HW;
        int r = d - z * HW;
        int y = r / W_SZ;
        int x = r - y * W_SZ;
        // 4 consecutive dense elems may cross a row boundary; handle scalar.
        int base = z * PLANEP;
        float vv[4] = {v.x, v.y, v.z, v.w};
#pragma unroll
        for (int j = 0; j < 4; j++) {
            int xx = x + j, yy = y, zz = base;
            if (xx >= W_SZ) { xx -= W_SZ; yy++; }
            if (yy >= H_SZ) { yy -= H_SZ; zz += PLANEP; }
            vol[zz + yy * ROWP + xx] = vv[j];
        }
    }
    if (tid < F_SZ) affs[tid] = *(const float4*)&g_aff[b * 80 + tid * 4];
    __syncthreads();

    if (tid >= 2 * HW) return;
    int g = (tid >= HW) ? 1 : 0;
    int p = tid - g * HW;
    int y = p / W_SZ;
    int x = p - y * W_SZ;
    float gx = (2.f / 17.f) * x - 1.f;
    float gy = (2.f / 17.f) * y - 1.f;
    float* ob = out + b * FHW + p;

    if (g == 0) {
        sample_one<0>(vol, affs, gx, gy, ob);
        sample_one<1>(vol, affs, gx, gy, ob);
        sample_one<2>(vol, affs, gx, gy, ob);
        sample_one<3>(vol, affs, gx, gy, ob);
        sample_one<4>(vol, affs, gx, gy, ob);
        sample_one<5>(vol, affs, gx, gy, ob);
        sample_one<6>(vol, affs, gx, gy, ob);
        sample_one<7>(vol, affs, gx, gy, ob);
        sample_one<8>(vol, affs, gx, gy, ob);
        sample_one<9>(vol, affs, gx, gy, ob);
    } else {
        sample_one<10>(vol, affs, gx, gy, ob);
        sample_one<11>(vol, affs, gx, gy, ob);
        sample_one<12>(vol, affs, gx, gy, ob);
        sample_one<13>(vol, affs, gx, gy, ob);
        sample_one<14>(vol, affs, gx, gy, ob);
        sample_one<15>(vol, affs, gx, gy, ob);
        sample_one<16>(vol, affs, gx, gy, ob);
        sample_one<17>(vol, affs, gx, gy, ob);
        sample_one<18>(vol, affs, gx, gy, ob);
        sample_one<19>(vol, affs, gx, gy, ob);
    }
}

// ---------------------------------------------------------------------------
extern "C" void kernel_launch(void* const* d_in, const int* in_sizes, int n_in,
                              void* d_out, int out_size)
{
    const float* fmap = (const float*)d_in[0];  // (4096, 20, 18, 18)
    const float* pc   = (const float*)d_in[1];  // (4096, 256)
    const float* W1   = (const float*)d_in[2];  // (256, 256)
    const float* b1   = (const float*)d_in[3];  // (256)
    const float* Ws   = (const float*)d_in[4];  // (256, 20)
    const float* bs   = (const float*)d_in[5];  // (20)
    const float* Wr   = (const float*)d_in[6];  // (256, 20)
    const float* br   = (const float*)d_in[7];  // (20)
    const float* Wt   = (const float*)d_in[8];  // (256, 40)
    const float* bt   = (const float*)d_in[9];  // (40)
    float* out = (float*)d_out;

    gemm_relu_kernel<<<dim3(B_SZ / 64, P_SZ / 64), 256>>>(pc, W1, b1);
    params_kernel<<<B_SZ / 16, 256>>>(Ws, bs, Wr, br, Wt, bt);
    sample_kernel<<<B_SZ, 672>>>(fmap, out);
}

// round 7
// speedup vs baseline: 1.5842x; 1.1562x over previous
#include <cuda_runtime.h>
#include <cuda_bf16.h>
#include <math.h>

// Shapes
#define B_SZ 4096
#define P_SZ 256
#define F_SZ 20
#define H_SZ 18
#define W_SZ 18
#define HW   (H_SZ * W_SZ)          // 324
#define FHW  (F_SZ * HW)            // 6480
#define PI_C 3.14159f

#define PS   328                    // zvol plane stride (floats, 16B aligned)

// Scratch (no allocations allowed; use device globals)
__device__ float g_h[B_SZ * P_SZ];          // relu(pc @ W1 + b1)
__device__ float g_aff[B_SZ * F_SZ * 4];    // per (b,f): u, v, Bx, By

// ---------------------------------------------------------------------------
// Kernel 1: h = relu(pc @ W1 + b1).  M=4096, N=256, K=256.
// ---------------------------------------------------------------------------
__global__ void __launch_bounds__(256) gemm_relu_kernel(
    const float* __restrict__ A,
    const float* __restrict__ W,
    const float* __restrict__ bias)
{
    const int BM = 64, BN = 64, BK = 16;
    __shared__ float As[BK][BM + 4];
    __shared__ float Bs[BK][BN];

    int tid = threadIdx.x;
    int tx = tid & 15;
    int ty = tid >> 4;
    int row0 = blockIdx.x * BM;
    int col0 = blockIdx.y * BN;

    float acc[4][4];
#pragma unroll
    for (int i = 0; i < 4; i++)
#pragma unroll
        for (int j = 0; j < 4; j++) acc[i][j] = 0.f;

    for (int k0 = 0; k0 < P_SZ; k0 += BK) {
        {
            int m  = tid >> 2;
            int kq = (tid & 3) << 2;
            float4 v = *(const float4*)&A[(row0 + m) * P_SZ + k0 + kq];
            As[kq + 0][m] = v.x;
            As[kq + 1][m] = v.y;
            As[kq + 2][m] = v.z;
            As[kq + 3][m] = v.w;
        }
        {
            int k = tid >> 4;
            int n = (tid & 15) << 2;
            *(float4*)&Bs[k][n] = *(const float4*)&W[(k0 + k) * P_SZ + col0 + n];
        }
        __syncthreads();

#pragma unroll
        for (int k = 0; k < BK; k++) {
            float4 av = *(const float4*)&As[k][ty * 4];
            float4 bv = *(const float4*)&Bs[k][tx * 4];
            float a[4] = {av.x, av.y, av.z, av.w};
            float b[4] = {bv.x, bv.y, bv.z, bv.w};
#pragma unroll
            for (int i = 0; i < 4; i++)
#pragma unroll
                for (int j = 0; j < 4; j++)
                    acc[i][j] = fmaf(a[i], b[j], acc[i][j]);
        }
        __syncthreads();
    }

    int c = col0 + tx * 4;
    float4 bb = *(const float4*)&bias[c];
#pragma unroll
    for (int i = 0; i < 4; i++) {
        int r = row0 + ty * 4 + i;
        float4 v;
        v.x = fmaxf(acc[i][0] + bb.x, 0.f);
        v.y = fmaxf(acc[i][1] + bb.y, 0.f);
        v.z = fmaxf(acc[i][2] + bb.z, 0.f);
        v.w = fmaxf(acc[i][3] + bb.w, 0.f);
        *(float4*)&g_h[r * P_SZ + c] = v;
    }
}

// ---------------------------------------------------------------------------
// Kernel 2: raw = h @ [Ws|Wr|Wt] (4096x80, K=256) + activations.
// ---------------------------------------------------------------------------
__global__ void __launch_bounds__(256) params_kernel(
    const float* __restrict__ Ws, const float* __restrict__ bs,
    const float* __restrict__ Wr, const float* __restrict__ br,
    const float* __restrict__ Wt, const float* __restrict__ bt)
{
    __shared__ float hs[16][33];
    __shared__ float ws[32][80];
    __shared__ float raw[16][80];

    int tid = threadIdx.x;
    int b0 = blockIdx.x * 16;
    int ty = tid >> 4;
    int tx = tid & 15;

    float acc[5];
#pragma unroll
    for (int j = 0; j < 5; j++) acc[j] = 0.f;

    for (int k0 = 0; k0 < P_SZ; k0 += 32) {
        if (tid < 128) {
            int m  = tid >> 3;
            int kq = (tid & 7) << 2;
            float4 v = *(const float4*)&g_h[(b0 + m) * P_SZ + k0 + kq];
            hs[m][kq + 0] = v.x;
            hs[m][kq + 1] = v.y;
            hs[m][kq + 2] = v.z;
            hs[m][kq + 3] = v.w;
        }
        for (int i = tid; i < 32 * 80; i += 256) {
            int k = i / 80;
            int j = i - k * 80;
            int kk = k0 + k;
            float w;
            if (j < 20)       w = Ws[kk * 20 + j];
            else if (j < 40)  w = Wr[kk * 20 + (j - 20)];
            else              w = Wt[kk * 40 + (j - 40)];
            ws[k][j] = w;
        }
        __syncthreads();

#pragma unroll
        for (int k = 0; k < 32; k++) {
            float a = hs[ty][k];
#pragma unroll
            for (int j = 0; j < 5; j++)
                acc[j] = fmaf(a, ws[k][tx * 5 + j], acc[j]);
        }
        __syncthreads();
    }

#pragma unroll
    for (int j = 0; j < 5; j++) raw[ty][tx * 5 + j] = acc[j];
    __syncthreads();

    for (int o = tid; o < 16 * F_SZ; o += 256) {
        int bi = o / F_SZ, f = o - bi * F_SZ;
        float scale = 2.f / (1.f + expf(-(raw[bi][f] + bs[f])));
        float angle = tanhf(raw[bi][20 + f] + br[f]) * PI_C;
        float txn = tanhf(raw[bi][40 + 2 * f] + bt[2 * f]);
        float tyn = tanhf(raw[bi][41 + 2 * f] + bt[2 * f + 1]);
        float s, c;
        sincosf(angle, &s, &c);
        float4 r = make_float4(9.f * scale * c,
                               9.f * scale * s,
                               9.f * txn + 8.5f,
                               9.f * tyn + 8.5f);
        *(float4*)&g_aff[(b0 + bi) * 80 + f * 4] = r;
    }
}

// ---------------------------------------------------------------------------
// Kernel 3: sampling via z-prelerped planes.
//   Stage A (build): zvol[f] = w0(f)*fmap[z0(f)] + w1(f)*fmap[z1(f)]
//     - z weights depend only on f -> hoisted out of the per-pixel loop.
//     - built straight from global, coalesced float4 (re-reads hit L1).
//   Stage B (sample): pure 2D bilinear, 4 SMEM taps per output (was 8),
//     branchless clamp+mask.
// One CTA per batch, 672 threads; active thread = pixel x 10 channels.
// ---------------------------------------------------------------------------
__global__ void __launch_bounds__(672) sample_kernel(
    const float* __restrict__ fmap,   // (B, 20, 18, 18)
    float* __restrict__ out)          // (B, 20, 18, 18)
{
    __shared__ float zvol[F_SZ * PS];           // 26.2 KB
    __shared__ float4 affs[F_SZ];
    int b = blockIdx.x;
    int tid = threadIdx.x;

    // Stage A: build z-prelerped planes (20 * 81 = 1620 float4 outputs)
    const float4* fb4 = (const float4*)(fmap + b * FHW);
    for (int i = tid; i < F_SZ * (HW / 4); i += 672) {
        int f = i / (HW / 4);
        int j = i - f * (HW / 4);
        float iz = f * (20.f / 19.f) - 0.5f;
        float z0f = floorf(iz);
        int z0 = (int)z0f;
        float wz = iz - z0f;
        float w0 = (z0 >= 0) ? (1.f - wz) : 0.f;
        float w1 = (z0 + 1 <= F_SZ - 1) ? wz : 0.f;
        int zc0 = max(z0, 0);
        int zc1 = min(z0 + 1, F_SZ - 1);
        float4 a = fb4[zc0 * (HW / 4) + j];
        float4 c = fb4[zc1 * (HW / 4) + j];
        float4 r;
        r.x = w0 * a.x + w1 * c.x;
        r.y = w0 * a.y + w1 * c.y;
        r.z = w0 * a.z + w1 * c.z;
        r.w = w0 * a.w + w1 * c.w;
        *(float4*)&zvol[f * PS + j * 4] = r;
    }
    if (tid < F_SZ) affs[tid] = *(const float4*)&g_aff[b * 80 + tid * 4];
    __syncthreads();

    // Stage B: 2D bilinear sampling
    if (tid >= 2 * HW) return;
    int g = (tid >= HW) ? 1 : 0;
    int p = tid - g * HW;
    int y = p / W_SZ;
    int x = p - y * W_SZ;
    float gx = (2.f / 17.f) * x - 1.f;
    float gy = (2.f / 17.f) * y - 1.f;
    int fbase = g * 10;
    float* ob = out + b * FHW + p;

#pragma unroll
    for (int i = 0; i < 10; i++) {
        int f = fbase + i;
        float4 A = affs[f];
        float ix = fmaf(A.x, gx, fmaf(-A.y, gy, A.z));
        float iy = fmaf(A.y, gx, fmaf(A.x, gy, A.w));

        float x0f = floorf(ix), y0f = floorf(iy);
        float wx = ix - x0f, wy = iy - y0f;
        int x0 = (int)x0f, y0 = (int)y0f;

        int xc0 = min(max(x0, 0), W_SZ - 1);
        int xc1 = min(max(x0 + 1, 0), W_SZ - 1);
        int yc0 = min(max(y0, 0), H_SZ - 1);
        int yc1 = min(max(y0 + 1, 0), H_SZ - 1);
        float wx0 = ((unsigned)x0       < (unsigned)W_SZ) ? (1.f - wx) : 0.f;
        float wx1 = ((unsigned)(x0 + 1) < (unsigned)W_SZ) ? wx         : 0.f;
        float wy0 = ((unsigned)y0       < (unsigned)H_SZ) ? (1.f - wy) : 0.f;
        float wy1 = ((unsigned)(y0 + 1) < (unsigned)H_SZ) ? wy         : 0.f;

        const float* pf = zvol + f * PS;
        int r0 = yc0 * W_SZ, r1 = yc1 * W_SZ;
        float v00 = pf[r0 + xc0], v01 = pf[r0 + xc1];
        float v10 = pf[r1 + xc0], v11 = pf[r1 + xc1];

        float top = fmaf(wx0, v00, wx1 * v01);
        float bot = fmaf(wx0, v10, wx1 * v11);
        ob[f * HW] = fmaf(wy0, top, wy1 * bot);
    }
}

// ---------------------------------------------------------------------------
extern "C" void kernel_launch(void* const* d_in, const int* in_sizes, int n_in,
                              void* d_out, int out_size)
{
    const float* fmap = (const float*)d_in[0];  // (4096, 20, 18, 18)
    const float* pc   = (const float*)d_in[1];  // (4096, 256)
    const float* W1   = (const float*)d_in[2];  // (256, 256)
    const float* b1   = (const float*)d_in[3];  // (256)
    const float* Ws   = (const float*)d_in[4];  // (256, 20)
    const float* bs   = (const float*)d_in[5];  // (20)
    const float* Wr   = (const float*)d_in[6];  // (256, 20)
    const float* br   = (const float*)d_in[7];  // (20)
    const float* Wt   = (const float*)d_in[8];  // (256, 40)
    const float* bt   = (const float*)d_in[9];  // (40)
    float* out = (float*)d_out;

    gemm_relu_kernel<<<dim3(B_SZ / 64, P_SZ / 64), 256>>>(pc, W1, b1);
    params_kernel<<<B_SZ / 16, 256>>>(Ws, bs, Wr, br, Wt, bt);
    sample_kernel<<<B_SZ, 672>>>(fmap, out);
}